// round 3
// baseline (speedup 1.0000x reference)
#include <cuda_runtime.h>
#include <cstdint>
#include <cstddef>

#define Bz 32
#define Dd 1024
#define Ff 512
#define Hh 16
#define Oo 4
#define FC 4096

// Deterministic scratch (no device allocation allowed)
__device__ float g_logits[Oo * Bz * Hh * Ff];        // [o][b][h][f]  4 MB
__device__ float g_hcat_part[8 * Bz * FC];           // [chunk][b][o*1024+d]
__device__ float g_hcat[Bz * FC];                    // [b][o*1024+d]
__device__ float g_hidden_part[16 * Bz * FC];        // [kblk][b][j]

// ---------------------------------------------------------------------------
// Kernel A: logits[o,b,h,f] = (x[f,b,h,:] . q[o,h,:]) / 8, masked to -50
// Block = (b, 8-frame tile), 512 threads. q and x staged in padded smem:
//   q rows padded to 67 floats  -> bank (3*oh+s)%32, conflict-free over 32 lanes
//   x rows padded to 66 floats  -> bank (2*h+s)%32, conflict-free (o-pairs bcast)
// ---------------------------------------------------------------------------
__global__ void k_logits(const float* __restrict__ x, const int* __restrict__ nfp,
                         const float* __restrict__ q) {
    extern __shared__ float sm[];
    float* qs = sm;                 // 64 * 67
    float* xs = sm + 64 * 67;       // 8 * (16*66) = 8 * 1056
    int b  = blockIdx.x;
    int f0 = blockIdx.y * 8;
    int t  = threadIdx.x;
    int nf = nfp[b];

    for (int i = t; i < 64 * 64; i += 512)
        qs[(i >> 6) * 67 + (i & 63)] = q[i];

    for (int i = t; i < 8 * 1024; i += 512) {
        int ff = i >> 10, j = i & 1023;
        if (f0 + ff < nf)
            xs[ff * 1056 + (j >> 6) * 66 + (j & 63)] =
                x[((size_t)(f0 + ff) * Bz + b) * Dd + j];
    }
    __syncthreads();

    int fl = t >> 6;
    int oh = t & 63;
    int o = oh >> 4, h = oh & 15;
    int f = f0 + fl;

    float acc;
    if (f >= nf) {
        acc = -50.0f;
    } else {
        const float* xp = xs + fl * 1056 + h * 66;
        const float* qp = qs + oh * 67;
        float a = 0.f;
#pragma unroll
        for (int s = 0; s < 64; s++) a = fmaf(xp[s], qp[s], a);
        acc = a * 0.125f;
    }
    g_logits[((size_t)(o * Bz + b) * Hh + h) * Ff + f] = acc;
}

// ---------------------------------------------------------------------------
// Kernel B: softmax over f (per (o,b,h) column, incl. the -50 masked entries),
// writes attn in reference layout [o][f][b][h].
// ---------------------------------------------------------------------------
__global__ void k_softmax(float* __restrict__ attn) {
    int ob = blockIdx.x;
    int o = ob >> 5, b = ob & 31;
    int t = threadIdx.x;           // 256
    int w = t >> 5, lane = t & 31;

    __shared__ float ls[Hh * Ff];  // 32 KB
    __shared__ float si[Hh];

    const float* src = g_logits + (size_t)(o * Bz + b) * Hh * Ff;
    for (int i = t; i < Hh * Ff; i += 256) ls[i] = src[i];
    __syncthreads();

    for (int hh = w; hh < Hh; hh += 8) {
        float* lp = ls + hh * Ff;
        float m = -1e30f;
        for (int k = lane; k < Ff; k += 32) m = fmaxf(m, lp[k]);
#pragma unroll
        for (int off = 16; off; off >>= 1)
            m = fmaxf(m, __shfl_xor_sync(0xffffffffu, m, off));
        float s = 0.f;
        for (int k = lane; k < Ff; k += 32) {
            float e = __expf(lp[k] - m);
            lp[k] = e;
            s += e;
        }
#pragma unroll
        for (int off = 16; off; off >>= 1)
            s += __shfl_xor_sync(0xffffffffu, s, off);
        if (lane == 0) si[hh] = 1.0f / s;
    }
    __syncthreads();

    float* dst = attn + (size_t)o * Ff * Bz * Hh + b * Hh;
    for (int i = t; i < Hh * Ff; i += 256) {
        int f = i >> 4, hh = i & 15;
        dst[(size_t)f * (Bz * Hh) + hh] = ls[hh * Ff + f] * si[hh];
    }
}

// ---------------------------------------------------------------------------
// Kernel C: partial weighted sums over 64-frame chunks (no atomics —
// deterministic). h_vid[o,b,d] = sum_f x[f,b,d] * attn[o,f,b,h(d)], f < nf.
// Block = (b, chunk), 1024 threads (one per d). attn chunk staged in smem;
// reads are warp-uniform (h constant per warp) -> broadcast LDS.
// ---------------------------------------------------------------------------
__global__ void k_wsum(const float* __restrict__ x, const int* __restrict__ nfp,
                       const float* __restrict__ attn) {
    int b = blockIdx.x;
    int c = blockIdx.y;
    int f0 = c * 64;
    int nf = nfp[b];
    int d = threadIdx.x;
    int h = d >> 6;

    __shared__ float as[4 * 64 * 16];   // [o][fl][h] 16 KB
    float a0 = 0.f, a1 = 0.f, a2 = 0.f, a3 = 0.f;

    if (f0 < nf) {
        for (int i = d; i < 4096; i += 1024) {
            int o = i >> 10, r = i & 1023;   // r = fl*16 + h
            as[i] = attn[(size_t)o * (Ff * Bz * Hh) +
                         (size_t)(f0 + (r >> 4)) * (Bz * Hh) + b * Hh + (r & 15)];
        }
        __syncthreads();
        int fe = min(64, nf - f0);
        const float* xp = x + ((size_t)f0 * Bz + b) * Dd + d;
        for (int fl = 0; fl < fe; fl++) {
            float xv = xp[(size_t)fl * (Bz * Dd)];
            int ai = fl * 16 + h;
            a0 = fmaf(xv, as[ai],        a0);
            a1 = fmaf(xv, as[1024 + ai], a1);
            a2 = fmaf(xv, as[2048 + ai], a2);
            a3 = fmaf(xv, as[3072 + ai], a3);
        }
    }
    float* p = g_hcat_part + ((size_t)c * Bz + b) * FC + d;
    p[0] = a0; p[1024] = a1; p[2048] = a2; p[3072] = a3;
}

// Reduce the 8 chunk partials into hcat[b][o*1024+d]
__global__ void k_csum() {
    int i = blockIdx.x * blockDim.x + threadIdx.x;   // Bz*FC = 131072
    float s = 0.f;
#pragma unroll
    for (int c = 0; c < 8; c++) s += g_hcat_part[(size_t)c * (Bz * FC) + i];
    g_hcat[i] = s;
}

// ---------------------------------------------------------------------------
// Kernel D: hidden_part[kb][b][j] = sum_{k in kb-range} hcat[b][k] * W1[k][j]
// 512 blocks (32 j-chunks x 16 k-chunks), 128 threads, acc[32] per thread.
// hcat tile transposed in smem [kl][b] (pad 36) -> inner loop: 1 LDG W1 +
// 8 broadcast LDS.128 + 32 FFMA per k.
// ---------------------------------------------------------------------------
__global__ void __launch_bounds__(128, 2) k_gemm1(const float* __restrict__ W1) {
    int t = threadIdx.x;                  // 128
    int j = blockIdx.x * 128 + t;
    int k0 = blockIdx.y * 256;

    __shared__ float hs[128 * 36];        // 18 KB, rows 16B-aligned
    float acc[32];
#pragma unroll
    for (int i = 0; i < 32; i++) acc[i] = 0.f;

    for (int kt = 0; kt < 2; kt++) {
        int kb = k0 + kt * 128;
        __syncthreads();
        for (int i = t; i < 32 * 128; i += 128) {
            int b = i >> 7, kl = i & 127;
            hs[kl * 36 + b] = g_hcat[(size_t)b * FC + kb + kl];
        }
        __syncthreads();
        const float* wp = W1 + (size_t)kb * FC + j;
#pragma unroll 4
        for (int kl = 0; kl < 128; kl++) {
            float w = wp[(size_t)kl * FC];
            const float4* hp = (const float4*)&hs[kl * 36];
#pragma unroll
            for (int q4 = 0; q4 < 8; q4++) {
                float4 hv = hp[q4];
                acc[q4 * 4 + 0] = fmaf(hv.x, w, acc[q4 * 4 + 0]);
                acc[q4 * 4 + 1] = fmaf(hv.y, w, acc[q4 * 4 + 1]);
                acc[q4 * 4 + 2] = fmaf(hv.z, w, acc[q4 * 4 + 2]);
                acc[q4 * 4 + 3] = fmaf(hv.w, w, acc[q4 * 4 + 3]);
            }
        }
    }
    float* dst = g_hidden_part + (size_t)blockIdx.y * (Bz * FC) + j;
#pragma unroll
    for (int b = 0; b < 32; b++) dst[(size_t)b * FC] = acc[b];
}

// ---------------------------------------------------------------------------
// Kernel E: out[b][n] = b2[n] + sum_j relu(sum_kb hidden_part + b1[j]) * W2[j][n]
// ---------------------------------------------------------------------------
__global__ void k_out(const float* __restrict__ b1, const float* __restrict__ W2,
                      const float* __restrict__ b2, float* __restrict__ out) {
    int b = blockIdx.x;
    int t = threadIdx.x;   // 256
    float a0 = 0.f, a1 = 0.f, a2 = 0.f, a3 = 0.f;

    for (int j = t; j < FC; j += 256) {
        float hv = b1[j];
#pragma unroll
        for (int kb = 0; kb < 16; kb++)
            hv += g_hidden_part[((size_t)kb * Bz + b) * FC + j];
        hv = fmaxf(hv, 0.f);
        float4 w = *(const float4*)(W2 + (size_t)j * 4);
        a0 = fmaf(hv, w.x, a0);
        a1 = fmaf(hv, w.y, a1);
        a2 = fmaf(hv, w.z, a2);
        a3 = fmaf(hv, w.w, a3);
    }
#pragma unroll
    for (int off = 16; off; off >>= 1) {
        a0 += __shfl_xor_sync(0xffffffffu, a0, off);
        a1 += __shfl_xor_sync(0xffffffffu, a1, off);
        a2 += __shfl_xor_sync(0xffffffffu, a2, off);
        a3 += __shfl_xor_sync(0xffffffffu, a3, off);
    }
    __shared__ float s[8][4];
    if ((t & 31) == 0) {
        int w = t >> 5;
        s[w][0] = a0; s[w][1] = a1; s[w][2] = a2; s[w][3] = a3;
    }
    __syncthreads();
    if (t < 4) {
        float r = 0.f;
#pragma unroll
        for (int w = 0; w < 8; w++) r += s[w][t];
        out[b * 4 + t] = r + b2[t];
    }
}

// ---------------------------------------------------------------------------
extern "C" void kernel_launch(void* const* d_in, const int* in_sizes, int n_in,
                              void* d_out, int out_size) {
    const float* x  = (const float*)d_in[0];
    const int*   nf = (const int*)  d_in[1];
    const float* q  = (const float*)d_in[2];
    const float* W1 = (const float*)d_in[3];
    const float* b1 = (const float*)d_in[4];
    const float* W2 = (const float*)d_in[5];
    const float* b2 = (const float*)d_in[6];

    float* out_p  = (float*)d_out;              // (B, 4) = 128 floats
    float* attn_p = out_p + Bz * Oo;            // (O, F, B, H) = 1,048,576 floats

    const int smemA = (64 * 67 + 8 * 1056) * 4; // 50944 B > 48 KB default
    cudaFuncSetAttribute(k_logits, cudaFuncAttributeMaxDynamicSharedMemorySize, smemA);

    dim3 gA(Bz, Ff / 8);
    k_logits<<<gA, 512, smemA>>>(x, nf, q);

    k_softmax<<<Oo * Bz, 256>>>(attn_p);

    dim3 gC(Bz, 8);
    k_wsum<<<gC, 1024>>>(x, nf, attn_p);

    k_csum<<<(Bz * FC) / 256, 256>>>();

    dim3 gD(FC / 128, 16);
    k_gemm1<<<gD, 128>>>(W1);

    k_out<<<Bz, 256>>>(b1, W2, b2, out_p);
}